// round 14
// baseline (speedup 1.0000x reference)
#include <cuda_runtime.h>

#define HH   512
#define WW   512
#define BB   4
#define CINC 55
#define NRr  30
#define NCc  20
#define NCELL 600
#define OUTX 57671680   // 4*55*512*512

// Scratch (device globals; no allocation)
__device__ float g_Stop[NCELL];
__device__ float g_Sbot[NCELL];
__device__ float g_topm[NCELL];
__device__ float g_sig[NCELL];
__device__ float g_wtsum[18];
// B fragments for mma.m16n8k8.tf32, 7 chunks:
// [d][tap][kc][lane*2+{0,1}] = tf32(W[n=lane/4][ch=8*kc+(lane%4)(+4)][tap])
//                              * (1+2^-11)   (A-truncation compensation)
__device__ float g_bfrag[3 * 25 * 7 * 64];

__device__ __forceinline__ unsigned f2tf32(float v) {
    unsigned r;
    asm("cvt.rna.tf32.f32 %0, %1;" : "=r"(r) : "f"(v));
    return r;
}

__device__ __forceinline__ void mma_k8(float c[4],
                                       unsigned a0, unsigned a1,
                                       unsigned a2, unsigned a3,
                                       unsigned b0, unsigned b1) {
    asm volatile(
        "mma.sync.aligned.m16n8k8.row.col.f32.tf32.tf32.f32 "
        "{%0,%1,%2,%3}, {%4,%5,%6,%7}, {%8,%9}, {%0,%1,%2,%3};"
        : "+f"(c[0]), "+f"(c[1]), "+f"(c[2]), "+f"(c[3])
        : "r"(a0), "r"(a1), "r"(a2), "r"(a3), "r"(b0), "r"(b1));
}

__device__ __forceinline__ void cp4(unsigned dst, const float* src) {
    asm volatile("cp.async.ca.shared.global [%0], [%1], 4;"
                 :: "r"(dst), "l"(src));
}
#define CP_COMMIT() asm volatile("cp.async.commit_group;")
#define CP_WAIT1()  asm volatile("cp.async.wait_group 1;")
#define CP_WAIT0()  asm volatile("cp.async.wait_group 0;")

// ---------------------------------------------------------------------------
// Kernel 1: zero cell accumulators; fold top head (36->18 channel-sum);
// build lane-ordered k8 tf32 B-fragments with (1+2^-11) compensation.
// ---------------------------------------------------------------------------
__global__ __launch_bounds__(256) void prep_kernel(
    const float* __restrict__ w1, const float* __restrict__ w2,
    const float* __restrict__ w3, const float* __restrict__ wt)
{
    int idx = blockIdx.x * 256 + threadIdx.x;
    if (idx < 16800) {                       // 3*25*7*32 lanes
        int lane = idx & 31;
        int t2   = idx >> 5;
        int kc   = t2 % 7;
        int t3   = t2 / 7;
        int kk   = t3 % 25;
        int d    = t3 / 25;
        const float* w = (d == 0) ? w1 : (d == 1 ? w2 : w3);
        int n   = lane >> 2;
        int klo = lane & 3;
        float v0 = 0.f, v1 = 0.f;
        if (n < 6) {
            int ch0 = kc * 8 + klo;
            int ch1 = ch0 + 4;
            if (ch0 < CINC) v0 = w[(n * CINC + ch0) * 25 + kk] * 1.00048828125f;
            if (ch1 < CINC) v1 = w[(n * CINC + ch1) * 25 + kk] * 1.00048828125f;
        }
        int base = ((d * 25 + kk) * 7 + kc) * 64 + lane * 2;
        g_bfrag[base]     = __uint_as_float(f2tf32(v0));
        g_bfrag[base + 1] = __uint_as_float(f2tf32(v1));
    } else if (idx < 16800 + NCELL) {
        int t = idx - 16800;
        g_Stop[t] = 0.f;
        g_Sbot[t] = 0.f;
    } else if (idx < 16800 + NCELL + 18) {
        int t = idx - 16800 - NCELL;
        float s = 0.f;
        #pragma unroll 4
        for (int c = 0; c < 36; c++) s += wt[c * 18 + t];
        g_wtsum[t] = s;
    }
}

// ---------------------------------------------------------------------------
// Kernel 2: TF32 shift-GEMM dilated conv, cp.async double-buffered,
// pair-interleaved SMEM planes. Per block: one (batch, dilation), 32x16
// pixel tile. 7 chunks of 8 channels stored as 4 pair-planes of float2 =
// (ch k, ch k+4) per pixel -> each mma.m16n8k8 needs just 2 LDS.64.
// Pair-plane word stride 2472 (=8 mod 32) -> conflict-free warp loads.
// Both buffers pre-zeroed once; channel-pad words explicitly zeroed.
// ---------------------------------------------------------------------------
#define PPW   2472              // pair-plane stride in 4B words (2*1236)
#define BUFW  (4 * PPW)         // one buffer: 4 pair-planes (words)

extern __shared__ unsigned smu[];

template <int D>
__device__ __forceinline__ void conv_body(
    const float* __restrict__ x,
    const float* __restrict__ bias6,
    float* __restrict__ out, int b, int gx0, int gy0)
{
    constexpr int PAD = 2 * D;
    constexpr int SW  = 32 + 4 * D;
    constexpr int SH  = 16 + 4 * D;
    constexpr int OCB = 36 + 6 * (D - 1);

    const int tid  = threadIdx.x;
    const int lane = tid & 31;
    const int w    = tid >> 5;

    unsigned smb;
    asm("{.reg .u64 t; cvta.to.shared.u64 t, %1; cvt.u32.u64 %0, t;}"
        : "=r"(smb) : "l"(smu));

    // pre-zero both buffers once (halo cells stay zero for all chunks)
    for (int i = tid; i < 2 * BUFW; i += 256) smu[i] = 0u;
    __syncthreads();

    const float* xb = x + (((size_t)b * CINC) << 18)
                        + ((gy0 - PAD) << 9) + (gx0 - PAD);

    // stage chunk kc: 8 channels -> 4 pair-planes of (ch k, ch k+4)
    auto stage = [&](int kc) {
        const int bo = (kc & 1) * BUFW;
        #pragma unroll
        for (int p = 0; p < 8; p++) {
            const int ch   = kc * 8 + p;
            const int k    = p & 3;
            const int wsel = p >> 2;
            if (ch < CINC) {
                const float* src = xb + ((size_t)ch << 18);
                #pragma unroll
                for (int rr = 0; rr < (SH + 7) / 8; rr++) {
                    const int row = w + rr * 8;
                    if (row < SH) {
                        const int gy = gy0 - PAD + row;
                        const bool rok = (unsigned)gy < 512u;
                        #pragma unroll
                        for (int ci = 0; ci < (SW + 31) / 32; ci++) {
                            const int cc = lane + ci * 32;
                            if (cc < SW) {
                                const int gx = gx0 - PAD + cc;
                                if (rok && (unsigned)gx < 512u)
                                    cp4(smb + 4u * (bo + k * PPW +
                                            (row * SW + cc) * 2 + wsel),
                                        src + (row << 9) + cc);
                            }
                        }
                    }
                }
            } else {
                // channel padding: zero this word-plane (buffer is reused)
                for (int i = tid; i < SH * SW; i += 256)
                    smu[bo + k * PPW + i * 2 + wsel] = 0u;
            }
        }
    };

    // mt = (row-pair bit | span bit): out_row = w*2+(mt>>1), x-span = (mt&1)*16
    int mtoff[4];
    #pragma unroll
    for (int mt = 0; mt < 4; mt++)
        mtoff[mt] = (lane & 3) * PPW +
                    (((w * 2 + (mt >> 1)) + PAD) * SW +
                     (mt & 1) * 16 + (lane >> 2) + PAD) * 2
                    - (PAD * SW + PAD) * 2;   // tap offsets add ky*D*SW+kx*D

    float acc[4][4];
    #pragma unroll
    for (int mt = 0; mt < 4; mt++)
        #pragma unroll
        for (int j = 0; j < 4; j++) acc[mt][j] = 0.f;

    stage(0);
    CP_COMMIT();

    for (int kc = 0; kc < 7; kc++) {
        if (kc < 6) {
            stage(kc + 1);
            CP_COMMIT();
            CP_WAIT1();
        } else {
            CP_WAIT0();
        }
        __syncthreads();

        const unsigned* sb = smu + (kc & 1) * BUFW;
        #pragma unroll 5
        for (int kk = 0; kk < 25; kk++) {
            float2 bf = *(const float2*)&g_bfrag[
                (((D - 1) * 25 + kk) * 7 + kc) * 64 + lane * 2];
            unsigned b0 = __float_as_uint(bf.x);
            unsigned b1 = __float_as_uint(bf.y);
            const int tapw = ((kk / 5) * D * SW + (kk % 5) * D) * 2;
            #pragma unroll
            for (int mt = 0; mt < 4; mt++) {
                const unsigned* ap = sb + mtoff[mt] + tapw;
                uint2 lo = *(const uint2*)ap;          // (a0, a2) @ pixel
                uint2 hi = *(const uint2*)(ap + 16);   // (a1, a3) @ pixel+8
                mma_k8(acc[mt], lo.x, hi.x, lo.y, hi.y, b0, b1);
            }
        }
        __syncthreads();
    }

    // epilogue: bias + relu, scalar feat stores (C-frag layout)
    const int n0 = (lane & 3) * 2;
    if (n0 < 6) {
        float bi0 = __ldg(&bias6[n0]);
        float bi1 = __ldg(&bias6[n0 + 1]);
        const size_t ch0base = ((size_t)(b * CINC + OCB + n0))     << 18;
        const size_t ch1base = ((size_t)(b * CINC + OCB + n0 + 1)) << 18;
        #pragma unroll
        for (int mt = 0; mt < 4; mt++) {
            int y  = gy0 + w * 2 + (mt >> 1);
            int gx = gx0 + (mt & 1) * 16 + (lane >> 2);
            unsigned pix = ((unsigned)y << 9) + (unsigned)gx;
            out[ch0base + pix]     = fmaxf(acc[mt][0] + bi0, 0.f);
            out[ch1base + pix]     = fmaxf(acc[mt][1] + bi1, 0.f);
            out[ch0base + pix + 8] = fmaxf(acc[mt][2] + bi0, 0.f);
            out[ch1base + pix + 8] = fmaxf(acc[mt][3] + bi1, 0.f);
        }
    }
}

__global__ __launch_bounds__(256, 2) void conv_kernel(
    const float* __restrict__ x,
    const float* __restrict__ b1, const float* __restrict__ b2,
    const float* __restrict__ b3,
    float* __restrict__ out)
{
    const int z   = blockIdx.z;
    const int b   = z / 3;
    const int d   = z - b * 3;
    const int gx0 = blockIdx.x * 32;
    const int gy0 = blockIdx.y * 16;
    if (d == 0)      conv_body<1>(x, b1, out, b, gx0, gy0);
    else if (d == 1) conv_body<2>(x, b2, out, b, gx0, gy0);
    else             conv_body<3>(x, b3, out, b, gx0, gy0);
}

// ---------------------------------------------------------------------------
// Kernel 3: head reduction — read feat (channels 36..53) back (L2-hot),
// form per-pixel channel-sum head values, accumulate into per-cell sums.
// ---------------------------------------------------------------------------
__global__ __launch_bounds__(256) void reduce_kernel(
    const int* __restrict__ row_seg, const int* __restrict__ col_seg,
    const float* __restrict__ wbv, const float* __restrict__ out)
{
    __shared__ float cT[NCELL], cB[NCELL];
    __shared__ float swt[18], swb[18];
    const int tid = threadIdx.x;
    for (int t = tid; t < NCELL; t += 256) { cT[t] = 0.f; cB[t] = 0.f; }
    if (tid < 18) { swt[tid] = g_wtsum[tid]; swb[tid] = __ldg(&wbv[tid]); }
    __syncthreads();

    unsigned i  = blockIdx.x * 256u + tid;
    unsigned x4 = (i & 127u) << 2;
    unsigned y  = (i >> 7) & 511u;
    unsigned b  = i >> 16;
    float st0 = 0.f, st1 = 0.f, st2 = 0.f, st3 = 0.f;
    float sb0 = 0.f, sb1 = 0.f, sb2 = 0.f, sb3 = 0.f;
    const size_t base = ((size_t)(b * CINC + 36) << 18) + (y << 9) + x4;
    #pragma unroll
    for (int j = 0; j < 18; j++) {
        float4 f = *(const float4*)&out[base + ((size_t)j << 18)];
        float wj = swt[j], vj = swb[j];
        st0 = fmaf(wj, f.x, st0); st1 = fmaf(wj, f.y, st1);
        st2 = fmaf(wj, f.z, st2); st3 = fmaf(wj, f.w, st3);
        sb0 = fmaf(vj, f.x, sb0); sb1 = fmaf(vj, f.y, sb1);
        sb2 = fmaf(vj, f.z, sb2); sb3 = fmaf(vj, f.w, sb3);
    }
    const int rb = row_seg[y] * NCc;
    const int c0 = col_seg[x4],     c1 = col_seg[x4 + 1];
    const int c2 = col_seg[x4 + 2], c3 = col_seg[x4 + 3];
    atomicAdd(&cT[rb + c0], st0); atomicAdd(&cT[rb + c1], st1);
    atomicAdd(&cT[rb + c2], st2); atomicAdd(&cT[rb + c3], st3);
    atomicAdd(&cB[rb + c0], sb0); atomicAdd(&cB[rb + c1], sb1);
    atomicAdd(&cB[rb + c2], sb2); atomicAdd(&cB[rb + c3], sb3);
    __syncthreads();
    for (int t = tid; t < NCELL; t += 256) {
        float v0 = cT[t], v1 = cB[t];
        if (v0 != 0.f) atomicAdd(&g_Stop[t], v0);
        if (v1 != 0.f) atomicAdd(&g_Sbot[t], v1);
    }
}

// ---------------------------------------------------------------------------
// Kernel 4: finalize means (adding head biases) -> top_m, sigmoid(bot_m);
// write pools output.
// ---------------------------------------------------------------------------
__global__ __launch_bounds__(640) void finalize_kernel(
    const int* __restrict__ row_seg, const int* __restrict__ col_seg,
    const float* __restrict__ bt, const float* __restrict__ bb,
    float* __restrict__ out)
{
    __shared__ int rc[NRr];
    __shared__ int cc[NCc];
    int t = threadIdx.x;
    if (t < NRr) rc[t] = 0;
    if (t < NCc) cc[t] = 0;
    __syncthreads();
    if (t < 512) {
        atomicAdd(&rc[row_seg[t]], 1);
        atomicAdd(&cc[col_seg[t]], 1);
    }
    __syncthreads();
    if (t < NCELL) {
        float btsum = 0.f;
        for (int c = 0; c < 36; c++) btsum += bt[c];
        float bb0 = bb[0];
        int r = t / NCc, c = t - r * NCc;
        float pix = (float)(rc[r] * cc[c]);
        float tm = (g_Stop[t] + (float)BB * pix * btsum) / (pix * (float)(BB * 36));
        float bm = (g_Sbot[t] + (float)BB * pix * bb0) / (pix * (float)BB);
        g_topm[t] = tm;
        float sg = 1.f / (1.f + expf(-bm));
        g_sig[t] = sg;
        #pragma unroll
        for (int b = 0; b < BB; b++)
            out[OUTX + b * NCELL + t] = sg;
    }
}

// ---------------------------------------------------------------------------
// Kernel 5: broadcast fill of channels 0..35 (top_m) and 54 (sigmoid(bot_m)).
// ---------------------------------------------------------------------------
__global__ __launch_bounds__(256) void bcast_kernel(
    const int* __restrict__ row_seg, const int* __restrict__ col_seg,
    float* __restrict__ out)
{
    unsigned i  = blockIdx.x * 256u + threadIdx.x;   // over B*H*W/4
    unsigned x4 = (i & 127u) << 2;
    unsigned y  = (i >> 7) & 511u;
    unsigned b  = i >> 16;
    int rb = __ldg(&row_seg[y]) * NCc;
    int c0 = __ldg(&col_seg[x4]);
    int c1 = __ldg(&col_seg[x4 + 1]);
    int c2 = __ldg(&col_seg[x4 + 2]);
    int c3 = __ldg(&col_seg[x4 + 3]);
    float4 tv = make_float4(g_topm[rb + c0], g_topm[rb + c1],
                            g_topm[rb + c2], g_topm[rb + c3]);
    float4 sv = make_float4(g_sig[rb + c0], g_sig[rb + c1],
                            g_sig[rb + c2], g_sig[rb + c3]);
    unsigned base = ((b * (unsigned)CINC) << 18) + (y << 9) + x4;
    #pragma unroll
    for (int ch = 0; ch < 36; ch++)
        *(float4*)&out[base + ((unsigned)ch << 18)] = tv;
    *(float4*)&out[base + (54u << 18)] = sv;
}

// ---------------------------------------------------------------------------
extern "C" void kernel_launch(void* const* d_in, const int* in_sizes, int n_in,
                              void* d_out, int out_size) {
    const float* x       = (const float*)d_in[0];
    const int*   row_seg = (const int*)d_in[1];
    const int*   col_seg = (const int*)d_in[2];
    const float* w1 = (const float*)d_in[3];
    const float* b1 = (const float*)d_in[4];
    const float* w2 = (const float*)d_in[5];
    const float* b2 = (const float*)d_in[6];
    const float* w3 = (const float*)d_in[7];
    const float* b3 = (const float*)d_in[8];
    const float* wt = (const float*)d_in[9];
    const float* bt = (const float*)d_in[10];
    const float* wb = (const float*)d_in[11];
    const float* bb = (const float*)d_in[12];
    float* out = (float*)d_out;

    prep_kernel<<<69, 256>>>(w1, w2, w3, wt);

    const int smbytes = 2 * BUFW * 4;       // 79104
    cudaFuncSetAttribute(conv_kernel,
                         cudaFuncAttributeMaxDynamicSharedMemorySize, smbytes);
    dim3 grid(WW / 32, HH / 16, BB * 3);    // 16 x 32 x 12
    conv_kernel<<<grid, 256, smbytes>>>(x, b1, b2, b3, out);

    reduce_kernel<<<(BB * HH * WW / 4) / 256, 256>>>(row_seg, col_seg, wb, out);

    finalize_kernel<<<1, 640>>>(row_seg, col_seg, bt, bb, out);

    bcast_kernel<<<(BB * HH * WW / 4) / 256, 256>>>(row_seg, col_seg, out);
}

// round 15
// speedup vs baseline: 1.2940x; 1.2940x over previous
#include <cuda_runtime.h>

#define HH   512
#define WW   512
#define BB   4
#define CINC 55
#define NRr  30
#define NCc  20
#define NCELL 600
#define OUTX 57671680   // 4*55*512*512

// Scratch (device globals; no allocation)
__device__ float g_Stop[NCELL];
__device__ float g_Sbot[NCELL];
__device__ float g_topm[NCELL];
__device__ float g_sig[NCELL];
__device__ float g_wtsum[18];
// B fragments for mma.m16n8k8.tf32, 7 chunks:
// [d][tap][kc][lane*2+{0,1}] = tf32(W[n=lane/4][ch=8*kc+(lane%4)(+4)][tap])
//                              * (1+2^-11)   (A-truncation compensation)
__device__ float g_bfrag[3 * 25 * 7 * 64];

__device__ __forceinline__ unsigned f2tf32(float v) {
    unsigned r;
    asm("cvt.rna.tf32.f32 %0, %1;" : "=r"(r) : "f"(v));
    return r;
}

__device__ __forceinline__ void mma_k8(float c[4],
                                       unsigned a0, unsigned a1,
                                       unsigned a2, unsigned a3,
                                       unsigned b0, unsigned b1) {
    asm volatile(
        "mma.sync.aligned.m16n8k8.row.col.f32.tf32.tf32.f32 "
        "{%0,%1,%2,%3}, {%4,%5,%6,%7}, {%8,%9}, {%0,%1,%2,%3};"
        : "+f"(c[0]), "+f"(c[1]), "+f"(c[2]), "+f"(c[3])
        : "r"(a0), "r"(a1), "r"(a2), "r"(a3), "r"(b0), "r"(b1));
}

__device__ __forceinline__ void cp4(unsigned dst, const float* src) {
    asm volatile("cp.async.ca.shared.global [%0], [%1], 4;"
                 :: "r"(dst), "l"(src));
}
__device__ __forceinline__ void cp16(unsigned dst, const float* src) {
    asm volatile("cp.async.cg.shared.global [%0], [%1], 16;"
                 :: "r"(dst), "l"(src));
}
#define CP_COMMIT() asm volatile("cp.async.commit_group;")
#define CP_WAIT1()  asm volatile("cp.async.wait_group 1;")
#define CP_WAIT0()  asm volatile("cp.async.wait_group 0;")

// ---------------------------------------------------------------------------
// Kernel 1: zero cell accumulators; fold top head (36->18 channel-sum);
// build lane-ordered k8 tf32 B-fragments with (1+2^-11) compensation.
// ---------------------------------------------------------------------------
__global__ __launch_bounds__(256) void prep_kernel(
    const float* __restrict__ w1, const float* __restrict__ w2,
    const float* __restrict__ w3, const float* __restrict__ wt)
{
    int idx = blockIdx.x * 256 + threadIdx.x;
    if (idx < 16800) {                       // 3*25*7*32 lanes
        int lane = idx & 31;
        int t2   = idx >> 5;
        int kc   = t2 % 7;
        int t3   = t2 / 7;
        int kk   = t3 % 25;
        int d    = t3 / 25;
        const float* w = (d == 0) ? w1 : (d == 1 ? w2 : w3);
        int n   = lane >> 2;
        int klo = lane & 3;
        float v0 = 0.f, v1 = 0.f;
        if (n < 6) {
            int ch0 = kc * 8 + klo;
            int ch1 = ch0 + 4;
            if (ch0 < CINC) v0 = w[(n * CINC + ch0) * 25 + kk] * 1.00048828125f;
            if (ch1 < CINC) v1 = w[(n * CINC + ch1) * 25 + kk] * 1.00048828125f;
        }
        int base = ((d * 25 + kk) * 7 + kc) * 64 + lane * 2;
        g_bfrag[base]     = __uint_as_float(f2tf32(v0));
        g_bfrag[base + 1] = __uint_as_float(f2tf32(v1));
    } else if (idx < 16800 + NCELL) {
        int t = idx - 16800;
        g_Stop[t] = 0.f;
        g_Sbot[t] = 0.f;
    } else if (idx < 16800 + NCELL + 18) {
        int t = idx - 16800 - NCELL;
        float s = 0.f;
        #pragma unroll 4
        for (int c = 0; c < 36; c++) s += wt[c * 18 + t];
        g_wtsum[t] = s;
    }
}

// ---------------------------------------------------------------------------
// Kernel 2: TF32 shift-GEMM — ALL 3 dilations fused per block so x is
// staged ONCE (PAD=6 covers every dilation). Tile 32x16 outputs, 256 thr.
// 7 k8 chunks of 8 channel planes, double-buffered cp.async:
//   interior blocks (82%): 16B cp.async.cg, smem x-origin at col offset 8
//   (SW=48) so src & dst are 16B-aligned; edge blocks: guarded 4B path.
// Plane stride 1352 words (=8 mod 32) -> conflict-free A-fragment LDS
// (pattern {0,8,16,24}+row covers all banks; +4-plane and +8 offsets
// preserve it). Inner: d x 25 taps x 4 m-tiles, mma.m16n8k8, acc[3][4][4].
// ---------------------------------------------------------------------------
#define PL    1352              // plane stride in words (28 rows * 48 + pad)
#define SWW   48                // staged row width (words)
#define SHH   28                // staged rows (16 + 2*6)
#define BUFW  (8 * PL)          // one chunk buffer (words)

extern __shared__ unsigned smu[];

__global__ __launch_bounds__(256, 2) void conv_kernel(
    const float* __restrict__ x,
    const float* __restrict__ b1, const float* __restrict__ b2,
    const float* __restrict__ b3,
    float* __restrict__ out)
{
    const int tid  = threadIdx.x;
    const int lane = tid & 31;
    const int w    = tid >> 5;
    const int gx0  = blockIdx.x * 32;
    const int gy0  = blockIdx.y * 16;
    const int b    = blockIdx.z;

    unsigned smb;
    asm("{.reg .u64 t; cvta.to.shared.u64 t, %1; cvt.u32.u64 %0, t;}"
        : "=r"(smb) : "l"(smu));

    const bool interior = (gx0 >= 32) && (gx0 <= 448) &&
                          (gy0 >= 16) && (gy0 <= 480);

    // pre-zero both buffers (edge-halo & never-written cells stay zero)
    for (int i = tid; i < 2 * BUFW; i += 256) smu[i] = 0u;
    __syncthreads();

    // smem col sc holds global x = gx0 + sc - 8 (valid data in sc=2..45);
    // smem row r holds global y = gy0 + r - 6.
    const float* xb = x + (((size_t)b * CINC) << 18);

    auto stage = [&](int kc) {
        const int bo = (kc & 1) * BUFW;
        if (interior) {
            // 8 planes * 28 rows * 12 16B-groups = 2688 ops
            #pragma unroll 1
            for (int i = tid; i < 8 * SHH * 12; i += 256) {
                int p   = i / (SHH * 12);
                int rem = i - p * (SHH * 12);
                int r   = rem / 12;
                int g   = rem - r * 12;
                int ch  = kc * 8 + p;
                unsigned dst = smb + 4u * (bo + p * PL + r * SWW + g * 4);
                if (ch < CINC) {
                    cp16(dst, xb + ((size_t)ch << 18) +
                              ((gy0 - 6 + r) << 9) + (gx0 - 8) + g * 4);
                } else {
                    *(uint4*)((char*)smu + (dst - smb)) = make_uint4(0, 0, 0, 0);
                }
            }
        } else {
            // guarded scalar path over the real halo cols (sc = 2..45)
            #pragma unroll 1
            for (int i = tid; i < 8 * SHH * 44; i += 256) {
                int p   = i / (SHH * 44);
                int rem = i - p * (SHH * 44);
                int r   = rem / 44;
                int c   = rem - r * 44;
                int ch  = kc * 8 + p;
                int sc  = c + 2;
                int gy  = gy0 + r - 6;
                int gx  = gx0 + sc - 8;
                int widx = bo + p * PL + r * SWW + sc;
                if (ch < CINC) {
                    if ((unsigned)gy < 512u && (unsigned)gx < 512u)
                        cp4(smb + 4u * widx,
                            xb + ((size_t)ch << 18) + (gy << 9) + gx);
                    // OOB cells: pre-zeroed & mask is chunk-invariant
                } else {
                    smu[widx] = 0u;
                }
            }
        }
    };

    // m-tile base word offsets (tap offset added later)
    int mtoff[4];
    #pragma unroll
    for (int mt = 0; mt < 4; mt++)
        mtoff[mt] = (lane & 3) * PL +
                    (w * 2 + (mt >> 1) + 6) * SWW +
                    (mt & 1) * 16 + (lane >> 2) + 8;

    float acc[3][4][4];
    #pragma unroll
    for (int d = 0; d < 3; d++)
        #pragma unroll
        for (int mt = 0; mt < 4; mt++)
            #pragma unroll
            for (int j = 0; j < 4; j++) acc[d][mt][j] = 0.f;

    stage(0);
    CP_COMMIT();

    for (int kc = 0; kc < 7; kc++) {
        if (kc < 6) {
            stage(kc + 1);
            CP_COMMIT();
            CP_WAIT1();
        } else {
            CP_WAIT0();
        }
        __syncthreads();

        const unsigned* sb = smu + (kc & 1) * BUFW;
        #pragma unroll
        for (int d = 0; d < 3; d++) {
            const int D = d + 1;
            const float* bfb = g_bfrag + ((d * 25) * 7 + kc) * 64 + lane * 2;
            #pragma unroll 5
            for (int kk = 0; kk < 25; kk++) {
                float2 bf = *(const float2*)(bfb + kk * 7 * 64);
                unsigned b0 = __float_as_uint(bf.x);
                unsigned b1 = __float_as_uint(bf.y);
                const int tap = (kk / 5 - 2) * D * SWW + (kk % 5 - 2) * D;
                #pragma unroll
                for (int mt = 0; mt < 4; mt++) {
                    const unsigned* ap = sb + mtoff[mt] + tap;
                    unsigned a0 = ap[0];
                    unsigned a1 = ap[8];
                    unsigned a2 = ap[4 * PL];
                    unsigned a3 = ap[4 * PL + 8];
                    mma_k8(acc[d][mt], a0, a1, a2, a3, b0, b1);
                }
            }
        }
        __syncthreads();
    }

    // epilogue: bias + relu, scalar feat stores (C-frag layout), all 3 d
    const int n0 = (lane & 3) * 2;
    if (n0 < 6) {
        const float* bp0[3] = { b1, b2, b3 };
        #pragma unroll
        for (int d = 0; d < 3; d++) {
            const int OCB = 36 + 6 * d;
            float bi0 = __ldg(&bp0[d][n0]);
            float bi1 = __ldg(&bp0[d][n0 + 1]);
            const size_t ch0base = ((size_t)(b * CINC + OCB + n0))     << 18;
            const size_t ch1base = ((size_t)(b * CINC + OCB + n0 + 1)) << 18;
            #pragma unroll
            for (int mt = 0; mt < 4; mt++) {
                int y  = gy0 + w * 2 + (mt >> 1);
                int gx = gx0 + (mt & 1) * 16 + (lane >> 2);
                unsigned pix = ((unsigned)y << 9) + (unsigned)gx;
                out[ch0base + pix]     = fmaxf(acc[d][mt][0] + bi0, 0.f);
                out[ch1base + pix]     = fmaxf(acc[d][mt][1] + bi1, 0.f);
                out[ch0base + pix + 8] = fmaxf(acc[d][mt][2] + bi0, 0.f);
                out[ch1base + pix + 8] = fmaxf(acc[d][mt][3] + bi1, 0.f);
            }
        }
    }
}

// ---------------------------------------------------------------------------
// Kernel 3: head reduction — read feat (channels 36..53) back (L2-hot),
// form per-pixel channel-sum head values, accumulate into per-cell sums.
// ---------------------------------------------------------------------------
__global__ __launch_bounds__(256) void reduce_kernel(
    const int* __restrict__ row_seg, const int* __restrict__ col_seg,
    const float* __restrict__ wbv, const float* __restrict__ out)
{
    __shared__ float cT[NCELL], cB[NCELL];
    __shared__ float swt[18], swb[18];
    const int tid = threadIdx.x;
    for (int t = tid; t < NCELL; t += 256) { cT[t] = 0.f; cB[t] = 0.f; }
    if (tid < 18) { swt[tid] = g_wtsum[tid]; swb[tid] = __ldg(&wbv[tid]); }
    __syncthreads();

    unsigned i  = blockIdx.x * 256u + tid;
    unsigned x4 = (i & 127u) << 2;
    unsigned y  = (i >> 7) & 511u;
    unsigned b  = i >> 16;
    float st0 = 0.f, st1 = 0.f, st2 = 0.f, st3 = 0.f;
    float sb0 = 0.f, sb1 = 0.f, sb2 = 0.f, sb3 = 0.f;
    const size_t base = ((size_t)(b * CINC + 36) << 18) + (y << 9) + x4;
    #pragma unroll
    for (int j = 0; j < 18; j++) {
        float4 f = *(const float4*)&out[base + ((size_t)j << 18)];
        float wj = swt[j], vj = swb[j];
        st0 = fmaf(wj, f.x, st0); st1 = fmaf(wj, f.y, st1);
        st2 = fmaf(wj, f.z, st2); st3 = fmaf(wj, f.w, st3);
        sb0 = fmaf(vj, f.x, sb0); sb1 = fmaf(vj, f.y, sb1);
        sb2 = fmaf(vj, f.z, sb2); sb3 = fmaf(vj, f.w, sb3);
    }
    const int rb = row_seg[y] * NCc;
    const int c0 = col_seg[x4],     c1 = col_seg[x4 + 1];
    const int c2 = col_seg[x4 + 2], c3 = col_seg[x4 + 3];
    atomicAdd(&cT[rb + c0], st0); atomicAdd(&cT[rb + c1], st1);
    atomicAdd(&cT[rb + c2], st2); atomicAdd(&cT[rb + c3], st3);
    atomicAdd(&cB[rb + c0], sb0); atomicAdd(&cB[rb + c1], sb1);
    atomicAdd(&cB[rb + c2], sb2); atomicAdd(&cB[rb + c3], sb3);
    __syncthreads();
    for (int t = tid; t < NCELL; t += 256) {
        float v0 = cT[t], v1 = cB[t];
        if (v0 != 0.f) atomicAdd(&g_Stop[t], v0);
        if (v1 != 0.f) atomicAdd(&g_Sbot[t], v1);
    }
}

// ---------------------------------------------------------------------------
// Kernel 4: finalize means (adding head biases) -> top_m, sigmoid(bot_m);
// write pools output.
// ---------------------------------------------------------------------------
__global__ __launch_bounds__(640) void finalize_kernel(
    const int* __restrict__ row_seg, const int* __restrict__ col_seg,
    const float* __restrict__ bt, const float* __restrict__ bb,
    float* __restrict__ out)
{
    __shared__ int rc[NRr];
    __shared__ int cc[NCc];
    int t = threadIdx.x;
    if (t < NRr) rc[t] = 0;
    if (t < NCc) cc[t] = 0;
    __syncthreads();
    if (t < 512) {
        atomicAdd(&rc[row_seg[t]], 1);
        atomicAdd(&cc[col_seg[t]], 1);
    }
    __syncthreads();
    if (t < NCELL) {
        float btsum = 0.f;
        for (int c = 0; c < 36; c++) btsum += bt[c];
        float bb0 = bb[0];
        int r = t / NCc, c = t - r * NCc;
        float pix = (float)(rc[r] * cc[c]);
        float tm = (g_Stop[t] + (float)BB * pix * btsum) / (pix * (float)(BB * 36));
        float bm = (g_Sbot[t] + (float)BB * pix * bb0) / (pix * (float)BB);
        g_topm[t] = tm;
        float sg = 1.f / (1.f + expf(-bm));
        g_sig[t] = sg;
        #pragma unroll
        for (int b = 0; b < BB; b++)
            out[OUTX + b * NCELL + t] = sg;
    }
}

// ---------------------------------------------------------------------------
// Kernel 5: broadcast fill of channels 0..35 (top_m) and 54 (sigmoid(bot_m)).
// ---------------------------------------------------------------------------
__global__ __launch_bounds__(256) void bcast_kernel(
    const int* __restrict__ row_seg, const int* __restrict__ col_seg,
    float* __restrict__ out)
{
    unsigned i  = blockIdx.x * 256u + threadIdx.x;   // over B*H*W/4
    unsigned x4 = (i & 127u) << 2;
    unsigned y  = (i >> 7) & 511u;
    unsigned b  = i >> 16;
    int rb = __ldg(&row_seg[y]) * NCc;
    int c0 = __ldg(&col_seg[x4]);
    int c1 = __ldg(&col_seg[x4 + 1]);
    int c2 = __ldg(&col_seg[x4 + 2]);
    int c3 = __ldg(&col_seg[x4 + 3]);
    float4 tv = make_float4(g_topm[rb + c0], g_topm[rb + c1],
                            g_topm[rb + c2], g_topm[rb + c3]);
    float4 sv = make_float4(g_sig[rb + c0], g_sig[rb + c1],
                            g_sig[rb + c2], g_sig[rb + c3]);
    unsigned base = ((b * (unsigned)CINC) << 18) + (y << 9) + x4;
    #pragma unroll
    for (int ch = 0; ch < 36; ch++)
        *(float4*)&out[base + ((unsigned)ch << 18)] = tv;
    *(float4*)&out[base + (54u << 18)] = sv;
}

// ---------------------------------------------------------------------------
extern "C" void kernel_launch(void* const* d_in, const int* in_sizes, int n_in,
                              void* d_out, int out_size) {
    const float* x       = (const float*)d_in[0];
    const int*   row_seg = (const int*)d_in[1];
    const int*   col_seg = (const int*)d_in[2];
    const float* w1 = (const float*)d_in[3];
    const float* b1 = (const float*)d_in[4];
    const float* w2 = (const float*)d_in[5];
    const float* b2 = (const float*)d_in[6];
    const float* w3 = (const float*)d_in[7];
    const float* b3 = (const float*)d_in[8];
    const float* wt = (const float*)d_in[9];
    const float* bt = (const float*)d_in[10];
    const float* wb = (const float*)d_in[11];
    const float* bb = (const float*)d_in[12];
    float* out = (float*)d_out;

    prep_kernel<<<69, 256>>>(w1, w2, w3, wt);

    const int smbytes = 2 * BUFW * 4;       // 86528
    cudaFuncSetAttribute(conv_kernel,
                         cudaFuncAttributeMaxDynamicSharedMemorySize, smbytes);
    dim3 grid(WW / 32, HH / 16, BB);        // 16 x 32 x 4
    conv_kernel<<<grid, 256, smbytes>>>(x, b1, b2, b3, out);

    reduce_kernel<<<(BB * HH * WW / 4) / 256, 256>>>(row_seg, col_seg, wb, out);

    finalize_kernel<<<1, 640>>>(row_seg, col_seg, bt, bb, out);

    bcast_kernel<<<(BB * HH * WW / 4) / 256, 256>>>(row_seg, col_seg, out);
}